// round 10
// baseline (speedup 1.0000x reference)
#include <cuda_runtime.h>

#define NN 100000
#define EE 1600000
#define SCAN_BLOCKS 98   // ceil(NN/1024)

typedef unsigned long long ull;

// ---------------- device scratch (no allocations allowed) ----------------
__device__ int g_cnt[NN];
__device__ int g_off[NN + 1];
__device__ int g_part[SCAN_BLOCKS];
__device__ int g_srcs[EE];
__device__ __align__(16) float g_ea[EE * 12];     // edge_attr, CSR slot order, padded to 48B rows
__device__ __align__(16) float g_xl[NN * 128];
__device__ __align__(16) float g_xr[NN * 128];
__device__ __align__(16) float g_h[NN * 64];

// ---------------- packed f32x2 helpers (Blackwell) ----------------
__device__ __forceinline__ ull pack2s(float v) {
    ull r; asm("mov.b64 %0, {%1, %1};" : "=l"(r) : "f"(v)); return r;
}
__device__ __forceinline__ ull fma2(ull a, ull b, ull c) {
    ull d; asm("fma.rn.f32x2 %0, %1, %2, %3;" : "=l"(d) : "l"(a), "l"(b), "l"(c)); return d;
}
__device__ __forceinline__ ull add2(ull a, ull b) {
    ull d; asm("add.rn.f32x2 %0, %1, %2;" : "=l"(d) : "l"(a), "l"(b)); return d;
}
__device__ __forceinline__ void unpack2(ull v, float& lo, float& hi) {
    asm("mov.b64 {%0, %1}, %2;" : "=f"(lo), "=f"(hi) : "l"(v));
}

// ---------------- CSR build ----------------
__global__ void k_zero_cnt() {
    int i = blockIdx.x * 256 + threadIdx.x;
    if (i < NN) g_cnt[i] = 0;
}

__global__ void k_count(const int* __restrict__ dst) {
    int e = blockIdx.x * 256 + threadIdx.x;   // exact grid: EE/256 blocks
    atomicAdd(&g_cnt[dst[e]], 1);
}

__global__ void k_scan1() {
    __shared__ int sh[1024];
    const int tid = threadIdx.x;
    const int i = blockIdx.x * 1024 + tid;
    int v = (i < NN) ? g_cnt[i] : 0;
    sh[tid] = v;
    __syncthreads();
    for (int ofs = 1; ofs < 1024; ofs <<= 1) {
        int t = (tid >= ofs) ? sh[tid - ofs] : 0;
        __syncthreads();
        sh[tid] += t;
        __syncthreads();
    }
    if (i < NN) g_off[i] = sh[tid] - v;           // exclusive within block
    if (tid == 1023) g_part[blockIdx.x] = sh[1023];
}

__global__ void k_scan2() {
    if (threadIdx.x == 0) {
        int run = 0;
        for (int b = 0; b < SCAN_BLOCKS; b++) { int t = g_part[b]; g_part[b] = run; run += t; }
        g_off[NN] = run;   // == EE
    }
}

__global__ void k_scan3() {
    const int i = blockIdx.x * 1024 + threadIdx.x;
    if (i < NN) {
        int v = g_off[i] + g_part[blockIdx.x];
        g_off[i] = v;
        g_cnt[i] = v;      // cursor for scatter
    }
}

// scatter edge -> CSR slot; permute edge_attr into 48B-padded slot-ordered rows
// (pad cols 10,11 never read as data; uniform LDG.128 in k_fused covers them harmlessly).
__global__ void k_scatter(const int* __restrict__ src, const int* __restrict__ dst,
                          const float* __restrict__ ea) {
    int e = blockIdx.x * 256 + threadIdx.x;   // exact grid
    int d = dst[e];
    int pos = atomicAdd(&g_cnt[d], 1);
    g_srcs[pos] = src[e];
    const float2* s2 = (const float2*)(ea + e * 10);   // 40B rows, 8B-aligned
    float2* d2 = (float2*)(g_ea + pos * 12);
#pragma unroll
    for (int k = 0; k < 5; k++) d2[k] = s2[k];
}

// ---------------- node transform: xl = act(in)@Wl + bl, xr = act(in)@Wr + br ----------------
template <int NIN, int HC, bool ACT, bool SRC_H>
__global__ void __launch_bounds__(128) k_xform(const float* __restrict__ X,
                                               const float* __restrict__ Wl,
                                               const float* __restrict__ bl,
                                               const float* __restrict__ Wr,
                                               const float* __restrict__ br) {
    __shared__ __align__(16) float xs[NIN * 16];
    const int tid = threadIdx.x;
    const int nb = blockIdx.x * 16;           // 16 nodes per block; NN%16==0
    const float* __restrict__ src = SRC_H ? g_h : X;

    for (int idx = tid; idx < NIN * 16; idx += HC) {
        int node = idx / NIN;
        int k = idx - node * NIN;
        float v = src[(nb + node) * NIN + k];
        if (ACT) v = fmaxf(v, 0.f) + 0.01f * fminf(v, 0.f);
        xs[k * 16 + node] = v;
    }
    __syncthreads();

    const int c = tid;                        // blockDim.x == HC
    ull accL[8], accR[8];
    {
        ull bl2 = pack2s(bl[c]);
        ull br2 = pack2s(br[c]);
#pragma unroll
        for (int j = 0; j < 8; j++) { accL[j] = bl2; accR[j] = br2; }
    }
#pragma unroll 4
    for (int k = 0; k < NIN; k++) {
        ull wl2 = pack2s(Wl[k * HC + c]);
        ull wr2 = pack2s(Wr[k * HC + c]);
#pragma unroll
        for (int j = 0; j < 8; j++) {
            ull xv = *(const ull*)&xs[k * 16 + 2 * j];   // broadcast LDS.64
            accL[j] = fma2(xv, wl2, accL[j]);
            accR[j] = fma2(xv, wr2, accR[j]);
        }
    }
#pragma unroll
    for (int j = 0; j < 8; j++) {
        float lo, hi;
        unpack2(accL[j], lo, hi);
        g_xl[(nb + 2 * j) * HC + c] = lo;
        g_xl[(nb + 2 * j + 1) * HC + c] = hi;
        unpack2(accR[j], lo, hi);
        g_xr[(nb + 2 * j) * HC + c] = lo;
        g_xr[(nb + 2 * j + 1) * HC + c] = hi;
    }
}

// ---------------- fused per-node: logits + softmax + aggregation ----------------
// warp per node; HEAD-PER-HALF-WARP layout: lanes 0-15 own head0's columns,
// lanes 16-31 own head1's. Per edge: 3 uniform LDG.128 for ea (no shfl broadcast),
// 1 coalesced LDG.128 (or .64) for xl, and ONE 4-step intra-half butterfly.
// No max-subtraction (logit magnitudes are O(10); exp is fp32-safe; quotient identical).
template <int HC, bool CONCAT, bool TO_H>
__global__ void __launch_bounds__(256) k_fused(const float* __restrict__ att,
                                               const float* __restrict__ We,
                                               const float* __restrict__ bias,
                                               float* __restrict__ out) {
    constexpr int CPL = HC / 32;    // columns per lane (4 for HC=128, 2 for HC=64)
    constexpr int UPL = CPL / 2;    // ulls per lane (2 or 1)
    const int lane = threadIdx.x & 31;
    const int n = blockIdx.x * 8 + (threadIdx.x >> 5);   // NN%8==0, exact
    const int half = lane >> 4;                          // = head index
    const int sub = lane & 15;
    const int colbase = half * (HC / 2) + sub * CPL;
    const int e0 = g_off[n], e1 = g_off[n + 1];
    float* __restrict__ dstbuf = TO_H ? g_h : out;

    // per-lane constants: this lane's CPL columns of We and att
    ull we2[10 * UPL];
    float attv[CPL];
#pragma unroll
    for (int k = 0; k < 10; k++)
#pragma unroll
        for (int u = 0; u < UPL; u++)
            we2[k * UPL + u] = *(const ull*)&We[k * HC + colbase + 2 * u];
#pragma unroll
    for (int j = 0; j < CPL; j++) attv[j] = att[colbase + j];

    // xr for THIS node (loaded once)
    ull xrv[UPL];
#pragma unroll
    for (int u = 0; u < UPL; u++)
        xrv[u] = *(const ull*)&g_xr[n * HC + colbase + 2 * u];

    float den = 0.f;
    ull acc[UPL];
#pragma unroll
    for (int u = 0; u < UPL; u++) acc[u] = 0ull;

#pragma unroll 1
    for (int t = e0; t < e1; t++) {
        const int s = g_srcs[t];                         // uniform
        // ea row: 3 uniform LDG.128 (48B padded row; cols 10,11 ignored)
        union { uint4 v[3]; float f[12]; } eau;
        const uint4* eap = (const uint4*)&g_ea[t * 12];
        eau.v[0] = eap[0]; eau.v[1] = eap[1]; eau.v[2] = eap[2];
        // xl gather: lane's CPL contiguous floats (warp covers full row, coalesced)
        ull xlv[UPL];
#pragma unroll
        for (int u = 0; u < UPL; u++)
            xlv[u] = *(const ull*)&g_xl[s * HC + colbase + 2 * u];

        // ef = ea @ We for this lane's columns
        ull ef[UPL];
#pragma unroll
        for (int u = 0; u < UPL; u++) ef[u] = 0ull;
#pragma unroll
        for (int k = 0; k < 10; k++) {
            ull ek = pack2s(eau.f[k]);
#pragma unroll
            for (int u = 0; u < UPL; u++)
                ef[u] = fma2(ek, we2[k * UPL + u], ef[u]);
        }

        // logit partial: leaky(xl+xr+ef) . att  over this lane's columns
        float sl = 0.f;
#pragma unroll
        for (int u = 0; u < UPL; u++) {
            float ux, uy;
            unpack2(add2(add2(xlv[u], xrv[u]), ef[u]), ux, uy);
            ux = fmaxf(ux, 0.f) + 0.2f * fminf(ux, 0.f);
            uy = fmaxf(uy, 0.f) + 0.2f * fminf(uy, 0.f);
            sl += ux * attv[2 * u] + uy * attv[2 * u + 1];
        }
        // 4-step intra-half butterfly: each half ends holding its head's logit
        sl += __shfl_xor_sync(0xffffffffu, sl, 8);
        sl += __shfl_xor_sync(0xffffffffu, sl, 4);
        sl += __shfl_xor_sync(0xffffffffu, sl, 2);
        sl += __shfl_xor_sync(0xffffffffu, sl, 1);

        float ex = __expf(sl);
        den += ex;
        ull ex2 = pack2s(ex);
#pragma unroll
        for (int u = 0; u < UPL; u++)
            acc[u] = fma2(ex2, xlv[u], acc[u]);
    }

    const float inv = 1.f / fmaxf(den, 1e-16f);

    if (CONCAT) {
        // layer 0 (HC=64, CPL=2): out width 64 = concat(head0 C=32, head1 C=32);
        // feature index == colbase+j, so every lane writes its own float2.
        float ax, ay;
        unpack2(acc[0], ax, ay);
        float2 o;
        o.x = ax * inv + bias[colbase];
        o.y = ay * inv + bias[colbase + 1];
        *(float2*)&dstbuf[n * 64 + colbase] = o;
    } else {
        // layers 1-2 (HC=128, CPL=4): mean over heads; lane j (half0) and lane j+16
        // (half1) hold the SAME output dims 4*sub..4*sub+3 -> one xor-16 combine per node.
        float r[4];
        unpack2(acc[0], r[0], r[1]);
        unpack2(acc[1], r[2], r[3]);
#pragma unroll
        for (int j = 0; j < 4; j++) r[j] *= inv;
#pragma unroll
        for (int j = 0; j < 4; j++) r[j] += __shfl_xor_sync(0xffffffffu, r[j], 16);
        if (half == 0) {
            float4 o;
            o.x = 0.5f * r[0] + bias[sub * 4];
            o.y = 0.5f * r[1] + bias[sub * 4 + 1];
            o.z = 0.5f * r[2] + bias[sub * 4 + 2];
            o.w = 0.5f * r[3] + bias[sub * 4 + 3];
            *(float4*)&dstbuf[n * 64 + sub * 4] = o;
        }
    }
}

// ---------------- launcher ----------------
extern "C" void kernel_launch(void* const* d_in, const int* in_sizes, int n_in,
                              void* d_out, int out_size) {
    const float* x     = (const float*)d_in[0];    // [N,79]
    const int*   ei    = (const int*)d_in[1];      // [2,E]
    const float* ea    = (const float*)d_in[2];    // [E,10]
    const float* Wl0   = (const float*)d_in[3];    // [79,64]
    const float* bl0   = (const float*)d_in[4];
    const float* Wr0   = (const float*)d_in[5];
    const float* br0   = (const float*)d_in[6];
    const float* We0   = (const float*)d_in[7];    // [10,64]
    const float* att0  = (const float*)d_in[8];    // [2,32]
    const float* bias0 = (const float*)d_in[9];    // [64]
    const float* Wl1   = (const float*)d_in[10];   // [2,64,128]
    const float* bl1   = (const float*)d_in[11];   // [2,128]
    const float* Wr1   = (const float*)d_in[12];
    const float* br1   = (const float*)d_in[13];
    const float* We1   = (const float*)d_in[14];   // [2,10,128]
    const float* att1  = (const float*)d_in[15];   // [2,2,64]
    const float* bias1 = (const float*)d_in[16];   // [2,64]
    float* out = (float*)d_out;                    // [N,64]

    const int* src = ei;
    const int* dst = ei + EE;

    // ---- CSR build (by dst) ----
    k_zero_cnt<<<(NN + 255) / 256, 256>>>();
    k_count<<<EE / 256, 256>>>(dst);
    k_scan1<<<SCAN_BLOCKS, 1024>>>();
    k_scan2<<<1, 32>>>();
    k_scan3<<<SCAN_BLOCKS, 1024>>>();
    k_scatter<<<EE / 256, 256>>>(src, dst, ea);

    // ---- layer 0: 79 -> (2 heads x 32), concat -> g_h ----
    k_xform<79, 64, false, false><<<NN / 16, 64>>>(x, Wl0, bl0, Wr0, br0);
    k_fused<64, true, true><<<NN / 8, 256>>>(att0, We0, bias0, out /*unused*/);

    // ---- layer 1: g_h -> g_h ----
    k_xform<64, 128, true, true><<<NN / 16, 128>>>(x /*unused*/, Wl1, bl1, Wr1, br1);
    k_fused<128, false, true><<<NN / 8, 256>>>(att1, We1, bias1, out /*unused*/);

    // ---- layer 2: g_h -> out ----
    k_xform<64, 128, true, true><<<NN / 16, 128>>>(x /*unused*/,
                                                   Wl1 + 64 * 128, bl1 + 128,
                                                   Wr1 + 64 * 128, br1 + 128);
    k_fused<128, false, false><<<NN / 8, 256>>>(att1 + 128, We1 + 10 * 128,
                                                bias1 + 64, out);
}